// round 5
// baseline (speedup 1.0000x reference)
#include <cuda_runtime.h>
#include <math.h>
#include <stdint.h>

#define NF 3000
#define NB 1500
#define RAD2 9.0f
#define INV_R (1.0f/3.0f)
#define CAP 256
#define EPSF 1e-8f
#define FOUR_OVER_PI 1.2732395447351628f

// ---------------- static device scratch (allocation-free rule) ----------------
__device__ float g_p1[NF*3];
__device__ float g_feat0[NF*9];
__device__ int   g_fcnt[NF];
__device__ int   g_fidx[NF*64];
__device__ int   g_fbase[NF*64];
__device__ float g_fw8[NF*512];
__device__ int   g_bcnt[NF];
__device__ int   g_bidx[NF*64];
__device__ int   g_bbase[NF*64];
__device__ float g_bw8[NF*512];
__device__ float g_A[(size_t)9000*6144];   // cellacc GEMM-A, reused each layer
__device__ float g_Abox[NF*64];
__device__ float g_cf[9000*32];
__device__ float g_co[NF*32];
__device__ float g_oc[9000*64];
__device__ float g_od[9000*64];
__device__ float g_out1[9000*96];
__device__ float g_out2[9000*96];
__device__ float g_h[9000*96];

// ---------------- geometry ----------------
__device__ __forceinline__ float sgnf(float v){ return (v>0.f)?1.f:((v<0.f)?-1.f:0.f); }

__device__ __forceinline__ void ball_to_cube(float x,float y,float z,float&obx,float&oby,float&obz){
    float sq = x*x+y*y+z*z;
    float norm = sqrtf(fmaxf(sq,EPSF));
    float xy_sq = x*x+y*y;
    bool polar = (1.25f*z*z) > xy_sq;
    float s_p = sqrtf(3.0f*norm/(norm+fabsf(z)+EPSF));
    float s_e = norm / sqrtf(fmaxf(xy_sq,EPSF));
    float cx = polar ? x*s_p : x*s_e;
    float cy = polar ? y*s_p : y*s_e;
    float cz = polar ? sgnf(z)*norm : 1.5f*z;
    float nxy = sqrtf(fmaxf(cx*cx+cy*cy,EPSF));
    bool xdom = fabsf(cy) <= fabsf(cx);
    float sx = (fabsf(cx) > EPSF) ? cx : 1.0f;
    float sy = (fabsf(cy) > EPSF) ? cy : 1.0f;
    float bx1 = sgnf(cx)*nxy;
    float by1 = bx1*FOUR_OVER_PI*atanf(cy/sx);
    float by2 = sgnf(cy)*nxy;
    float bx2 = by2*FOUR_OVER_PI*atanf(cx/sy);
    float bx = xdom ? bx1 : bx2;
    float by = xdom ? by1 : by2;
    if (cx*cx+cy*cy < EPSF){ bx=0.f; by=0.f; }
    if (sq < EPSF){ bx=0.f; by=0.f; cz=0.f; }
    obx=bx; oby=by; obz=cz;
}

// ---------------- prep: p1, fluid_feats, state output ----------------
__global__ void prep_kernel(const float* __restrict__ p0,const float* __restrict__ v0,
                            const float* __restrict__ a,const float* __restrict__ other,
                            const float* __restrict__ v0e,
                            float* __restrict__ p1,float* __restrict__ feat0,
                            float* __restrict__ outState){
    int i = blockIdx.x*blockDim.x + threadIdx.x;
    if (i >= NF) return;
#pragma unroll
    for (int d=0; d<3; d++){
        float vv0 = v0[i*3+d];
        float v1  = vv0 + 0.1f*a[i*3+d];
        float pp1 = p0[i*3+d] + 0.1f*(vv0+v1)*0.5f;
        p1[i*3+d]        = pp1;
        feat0[i*9+d]     = v1;
        feat0[i*9+3+d]   = other[i*3+d];
        feat0[i*9+6+d]   = v0e[i*3+d];
        outState[i*3+d]  = v0e[i*3+d];
    }
}

// ---------------- neighbor search: exact top-64 by (d2, idx) ----------------
__global__ void neigh_kernel(const float* __restrict__ pin, int Mp,
                             const float* __restrict__ pout,
                             const float* __restrict__ mask, int selfEx,
                             int* __restrict__ cntO, int* __restrict__ idxO,
                             int* __restrict__ baseO, float* __restrict__ w8O){
    __shared__ float cd2[CAP];
    __shared__ int   cid[CAP];
    __shared__ unsigned long long keys[CAP];
    __shared__ int scnt;
    int n = blockIdx.x, tid = threadIdx.x;
    float qx = pout[n*3], qy = pout[n*3+1], qz = pout[n*3+2];
    if (tid==0) scnt = 0;
    __syncthreads();
    for (int m = tid; m < Mp; m += blockDim.x){
        if (selfEx && m==n) continue;
        if (mask && !(mask[m] > 0.f)) continue;
        float dx = pin[m*3]-qx, dy = pin[m*3+1]-qy, dz = pin[m*3+2]-qz;
        float d2 = dx*dx + dy*dy + dz*dz;
        if (d2 <= RAD2){
            int p = atomicAdd(&scnt, 1);
            if (p < CAP){ cd2[p]=d2; cid[p]=m; }
        }
    }
    __syncthreads();
    int cn = min(scnt, CAP);
    for (int t = tid; t < CAP; t += blockDim.x)
        keys[t] = (t < cn) ? ((((unsigned long long)__float_as_uint(cd2[t]))<<32) | (unsigned)cid[t])
                           : 0xFFFFFFFFFFFFFFFFull;
    __syncthreads();
    // bitonic sort, 256 elems, 128 threads
    for (int k = 2; k <= CAP; k <<= 1){
        for (int j = k>>1; j > 0; j >>= 1){
            int i = ((tid & ~(j-1)) << 1) | (tid & (j-1));
            int ixj = i | j;
            bool asc = ((i & k) == 0);
            unsigned long long av = keys[i], bv = keys[ixj];
            if ((av > bv) == asc){ keys[i]=bv; keys[ixj]=av; }
            __syncthreads();
        }
    }
    int keep = min(cn, 64);
    if (tid==0) cntO[n] = keep;
    for (int t = tid; t < keep; t += blockDim.x){
        unsigned long long key = keys[t];
        int m = (int)(key & 0xFFFFFFFFull);
        float dx = pin[m*3]-qx, dy = pin[m*3+1]-qy, dz = pin[m*3+2]-qz;
        float ux = dx*INV_R, uy = dy*INV_R, uz = dz*INV_R;
        float r2 = ux*ux + uy*uy + uz*uz;
        float t1 = 1.f - r2;
        float win = fminf(fmaxf(t1*t1*t1, 0.f), 1.f);
        float bx, by, bz;
        ball_to_cube(ux, uy, uz, bx, by, bz);
        float cxx = fminf(fmaxf((bx*0.5f+0.5f)*3.f, 0.f), 3.f);
        float cyy = fminf(fmaxf((by*0.5f+0.5f)*3.f, 0.f), 3.f);
        float czz = fminf(fmaxf((bz*0.5f+0.5f)*3.f, 0.f), 3.f);
        int c0x = min((int)floorf(cxx), 2);
        int c0y = min((int)floorf(cyy), 2);
        int c0z = min((int)floorf(czz), 2);
        float fx = cxx - (float)c0x, fy = cyy - (float)c0y, fz = czz - (float)c0z;
        idxO[n*64+t]  = m;
        baseO[n*64+t] = (c0x*4 + c0y)*4 + c0z;
        float gx[2] = {1.f-fx, fx}, gy[2] = {1.f-fy, fy}, gz[2] = {1.f-fz, fz};
        int jj = 0;
        for (int i2=0;i2<2;i2++) for (int j2=0;j2<2;j2++) for (int l2=0;l2<2;l2++)
            w8O[n*512 + t*8 + (jj++)] = gx[i2]*gy[j2]*gz[l2]*win;
    }
}

// ---------------- scatter: build cellacc rows of A ----------------
// acc[cell*F + f]; F>=64: thread-private f-columns (no races, no sync in loop).
// F<64: parallelize over (corner,f) per neighbor with a sync per neighbor.
__global__ void scatter_kernel(const float* __restrict__ feats, int F, int C, int S,
                               const int* __restrict__ cnt, const int* __restrict__ nidx,
                               const int* __restrict__ nbase, const float* __restrict__ nw8,
                               float* __restrict__ A){
    extern __shared__ float acc[];           // 64*F floats
    __shared__ int sIdx[64]; __shared__ int sBase[64]; __shared__ float sW[512];
    int n = blockIdx.x, tid = threadIdx.x;
    int cn = cnt[n];
    for (int e = tid; e < 64*F; e += blockDim.x) acc[e] = 0.f;
    if (tid < cn){ sIdx[tid] = nidx[n*64+tid]; sBase[tid] = nbase[n*64+tid]; }
    for (int e = tid; e < cn*8; e += blockDim.x) sW[e] = nw8[n*512+e];
    __syncthreads();
    if (F >= 64){
        for (int k = 0; k < cn; k++){
            int ik = sIdx[k], b = sBase[k];
            float w0=sW[k*8+0],w1=sW[k*8+1],w2=sW[k*8+2],w3=sW[k*8+3];
            float w4=sW[k*8+4],w5=sW[k*8+5],w6=sW[k*8+6],w7=sW[k*8+7];
            const float* fp = feats + (size_t)ik*F;
            for (int f = tid; f < F; f += blockDim.x){
                float fv = fp[f];
                acc[(b+0)*F+f]  += w0*fv;
                acc[(b+1)*F+f]  += w1*fv;
                acc[(b+4)*F+f]  += w2*fv;
                acc[(b+5)*F+f]  += w3*fv;
                acc[(b+16)*F+f] += w4*fv;
                acc[(b+17)*F+f] += w5*fv;
                acc[(b+20)*F+f] += w6*fv;
                acc[(b+21)*F+f] += w7*fv;
            }
        }
    } else {
        const int coff[8] = {0,1,4,5,16,17,20,21};
        for (int k = 0; k < cn; k++){
            int ik = sIdx[k], b = sBase[k];
            for (int it = tid; it < 8*F; it += blockDim.x){
                int j = it / F, f = it - j*F;
                acc[(b+coff[j])*F+f] += sW[k*8+j] * feats[(size_t)ik*F+f];
            }
            __syncthreads();
        }
    }
    __syncthreads();
    // A[(n*S+s)*64C + l*C + c] = acc[l*F + s*C + c]
    int KC = 64*C;
    for (int e = tid; e < 64*F; e += blockDim.x){
        int l = e / F, f = e - l*F;
        int s = f / C, c = f - s*C;
        A[(size_t)(n*S+s)*KC + l*C + c] = acc[e];
    }
}

// ---------------- fp32 GEMM: C = A(MxK,row) @ B(KxN,row), N<=64, K%16==0 ----
__global__ void gemm_kernel(const float* __restrict__ A, const float* __restrict__ B,
                            float* __restrict__ Cc, int M, int N, int K){
    __shared__ float As[16][64];
    __shared__ float Bs[16][64];
    int tid = threadIdx.x;
    int bm = blockIdx.x * 64;
    int tm = tid >> 4, tn = tid & 15;
    float acc[4][4] = {};
    int arow = bm + (tid >> 2);
    int akq  = (tid & 3) * 4;
    int brow = tid >> 4;
    int bcol = (tid & 15) * 4;
    for (int k0 = 0; k0 < K; k0 += 16){
        float4 a4 = make_float4(0.f,0.f,0.f,0.f);
        if (arow < M) a4 = *(const float4*)(A + (size_t)arow*K + k0 + akq);
        float4 b4 = make_float4(0.f,0.f,0.f,0.f);
        if (bcol < N) b4 = *(const float4*)(B + (size_t)(k0+brow)*N + bcol);
        __syncthreads();
        int lr = tid >> 2;
        As[akq+0][lr] = a4.x; As[akq+1][lr] = a4.y; As[akq+2][lr] = a4.z; As[akq+3][lr] = a4.w;
        *(float4*)&Bs[brow][bcol] = b4;
        __syncthreads();
#pragma unroll
        for (int kk = 0; kk < 16; kk++){
            float4 av = *(const float4*)&As[kk][tm*4];
            float4 bv = *(const float4*)&Bs[kk][tn*4];
            float ar[4] = {av.x, av.y, av.z, av.w};
            float br[4] = {bv.x, bv.y, bv.z, bv.w};
#pragma unroll
            for (int i=0;i<4;i++)
#pragma unroll
                for (int j=0;j<4;j++) acc[i][j] += ar[i]*br[j];
        }
    }
#pragma unroll
    for (int i=0;i<4;i++){
        int r = bm + tm*4 + i;
        if (r >= M) continue;
#pragma unroll
        for (int j=0;j<4;j++){
            int c = tn*4 + j;
            if (c < N) Cc[(size_t)r*N + c] = acc[i][j];
        }
    }
}

// ---------------- dot kernel for small N (<=3) ----------------
__global__ void dotn_kernel(const float* __restrict__ A, const float* __restrict__ B,
                            float* __restrict__ Cc, int M, int N, int K){
    extern __shared__ float sB[];
    int tid = threadIdx.x;
    for (int i = tid; i < K*N; i += blockDim.x) sB[i] = B[i];
    __syncthreads();
    int w = tid >> 5, lane = tid & 31;
    int r = blockIdx.x * 8 + w;
    if (r >= M) return;
    float a0=0.f, a1=0.f, a2=0.f;
    const float* ap = A + (size_t)r*K;
    for (int k = lane; k < K; k += 32){
        float av = ap[k];
        a0 += av * sB[k*N+0];
        if (N > 1) a1 += av * sB[k*N+1];
        if (N > 2) a2 += av * sB[k*N+2];
    }
    for (int off=16; off; off>>=1){
        a0 += __shfl_down_sync(0xffffffffu, a0, off);
        a1 += __shfl_down_sync(0xffffffffu, a1, off);
        a2 += __shfl_down_sync(0xffffffffu, a2, off);
    }
    if (lane == 0){
        Cc[(size_t)r*N+0] = a0;
        if (N > 1) Cc[(size_t)r*N+1] = a1;
        if (N > 2) Cc[(size_t)r*N+2] = a2;
    }
}

// ---------------- elementwise ----------------
__global__ void relu_kernel(const float* __restrict__ in, float* __restrict__ out, int n){
    int i = blockIdx.x*blockDim.x + threadIdx.x;
    if (i < n) out[i] = fmaxf(in[i], 0.f);
}

__global__ void combine0_kernel(const float* __restrict__ co, const float* __restrict__ cf,
                                const float* __restrict__ feat0,
                                const float* __restrict__ b0o, const float* __restrict__ b0f,
                                const float* __restrict__ wdf, const float* __restrict__ bdf,
                                float* __restrict__ out){
    int e = blockIdx.x*blockDim.x + threadIdx.x;
    if (e >= 9000*96) return;
    int row = e / 96, o = e - row*96;
    int n = row / 3;
    float v;
    if (o < 32) v = co[n*32+o] + b0o[o];
    else if (o < 64) v = cf[(size_t)row*32 + (o-32)] + b0f[o-32];
    else {
        int oo = o - 64;
        v = bdf[oo];
        for (int c=0;c<3;c++) v += feat0[row*3+c]*wdf[c*32+oo];
    }
    out[e] = v;
}

__global__ void combine_kernel(const float* __restrict__ oc, const float* __restrict__ od,
                               const float* __restrict__ bc, const float* __restrict__ bd,
                               const float* __restrict__ prev, float* __restrict__ out, int C){
    int e = blockIdx.x*blockDim.x + threadIdx.x;
    if (e >= 9000*C) return;
    int o = e % C;
    float v = oc[e] + bc[o] + od[e] + bd[o];
    if (prev) v += prev[e];
    out[e] = v;
}

__global__ void final_kernel(const float* __restrict__ out4, const float* __restrict__ p1,
                             const float* __restrict__ p0, float* __restrict__ dout){
    int e = blockIdx.x*blockDim.x + threadIdx.x;
    if (e >= NF*3) return;
    int n = e/3, d = e - n*3;
    float pc0 = out4[(n*3+0)*3+d] * 0.25f * (1.0f/16.0f);
    float pc1 = out4[(n*3+1)*3+d] * 0.25f;
    float pc2 = out4[(n*3+2)*3+d] * 0.25f;
    float p_c = p1[e] + pc0;
    dout[e] = p_c;
    dout[9000 + e] = (p_c - p0[e]) / 0.1f;
    dout[18000 + n*6 + d]     = pc1;
    dout[18000 + n*6 + 3 + d] = pc2;
}

// ---------------- launch ----------------
extern "C" void kernel_launch(void* const* d_in, const int* in_sizes, int n_in,
                              void* d_out, int out_size){
    const float* v0e  = (const float*)d_in[1];
    const float* p0   = (const float*)d_in[2];
    const float* v0   = (const float*)d_in[3];
    const float* a    = (const float*)d_in[4];
    const float* other= (const float*)d_in[5];
    const float* box  = (const float*)d_in[6];
    const float* boxf = (const float*)d_in[7];
    const float* bmask= (const float*)d_in[9];
    const float* k0f  = (const float*)d_in[10];
    const float* b0f  = (const float*)d_in[11];
    const float* k0o  = (const float*)d_in[12];
    const float* b0o  = (const float*)d_in[13];
    const float* wdf  = (const float*)d_in[14];
    const float* bdf  = (const float*)d_in[15];
    const float *kc[4], *bcp[4], *wd[4], *bdp[4];
    if (in_sizes[18] == 262144){  // signature order: kc1..bc4 then wd1..bd4
        for (int i=0;i<4;i++){
            kc[i]=(const float*)d_in[16+2*i]; bcp[i]=(const float*)d_in[17+2*i];
            wd[i]=(const float*)d_in[24+2*i]; bdp[i]=(const float*)d_in[25+2*i];
        }
    } else {                      // dict order: kc_i, bc_i, wd_i, bd_i per layer
        for (int i=0;i<4;i++){
            kc[i]=(const float*)d_in[16+4*i]; bcp[i]=(const float*)d_in[17+4*i];
            wd[i]=(const float*)d_in[18+4*i]; bdp[i]=(const float*)d_in[19+4*i];
        }
    }
    float* dout = (float*)d_out;

    float *p1, *feat0, *A, *Abox, *cfb, *cob, *ocb, *odb, *o1, *o2, *hb, *fw8, *bw8;
    int *fcnt, *fidx, *fbase, *bcnt, *bidx, *bbase;
    cudaGetSymbolAddress((void**)&p1, g_p1);
    cudaGetSymbolAddress((void**)&feat0, g_feat0);
    cudaGetSymbolAddress((void**)&A, g_A);
    cudaGetSymbolAddress((void**)&Abox, g_Abox);
    cudaGetSymbolAddress((void**)&cfb, g_cf);
    cudaGetSymbolAddress((void**)&cob, g_co);
    cudaGetSymbolAddress((void**)&ocb, g_oc);
    cudaGetSymbolAddress((void**)&odb, g_od);
    cudaGetSymbolAddress((void**)&o1, g_out1);
    cudaGetSymbolAddress((void**)&o2, g_out2);
    cudaGetSymbolAddress((void**)&hb, g_h);
    cudaGetSymbolAddress((void**)&fw8, g_fw8);
    cudaGetSymbolAddress((void**)&bw8, g_bw8);
    cudaGetSymbolAddress((void**)&fcnt, g_fcnt);
    cudaGetSymbolAddress((void**)&fidx, g_fidx);
    cudaGetSymbolAddress((void**)&fbase, g_fbase);
    cudaGetSymbolAddress((void**)&bcnt, g_bcnt);
    cudaGetSymbolAddress((void**)&bidx, g_bidx);
    cudaGetSymbolAddress((void**)&bbase, g_bbase);

    cudaFuncSetAttribute(scatter_kernel, cudaFuncAttributeMaxDynamicSharedMemorySize, 80000);
    cudaFuncSetAttribute(dotn_kernel,    cudaFuncAttributeMaxDynamicSharedMemorySize, 50000);

    prep_kernel<<<(NF+127)/128, 128>>>(p0, v0, a, other, v0e, p1, feat0, dout + 36000);
    neigh_kernel<<<NF, 128>>>(p1, NF, p1, nullptr, 1, fcnt, fidx, fbase, fw8);
    neigh_kernel<<<NF, 128>>>(box, NB, p1, bmask, 0, bcnt, bidx, bbase, bw8);

    // layer 0: fluid cconv (C=3,S=3,F=9), box cconv (C=1,S=1,F=1), dense df in combine0
    scatter_kernel<<<NF, 256, 64*9*4>>>(feat0, 9, 3, 3, fcnt, fidx, fbase, fw8, A);
    gemm_kernel<<<(9000+63)/64, 256>>>(A, k0f, cfb, 9000, 32, 192);
    scatter_kernel<<<NF, 256, 64*1*4>>>(boxf, 1, 1, 1, bcnt, bidx, bbase, bw8, Abox);
    gemm_kernel<<<(3000+63)/64, 256>>>(Abox, k0o, cob, 3000, 32, 64);
    combine0_kernel<<<(9000*96+255)/256, 256>>>(cob, cfb, feat0, b0o, b0f, wdf, bdf, o1);

    int Cin[4]  = {96, 64, 64, 64};
    int Cout[4] = {64, 64, 64, 3};
    float* cur = o1; float* nxt = o2;
    for (int i=0;i<4;i++){
        int ci = Cin[i], co_ = Cout[i];
        relu_kernel<<<(9000*ci+255)/256, 256>>>(cur, hb, 9000*ci);
        scatter_kernel<<<NF, 256, (size_t)64*3*ci*4>>>(hb, 3*ci, ci, 3, fcnt, fidx, fbase, fw8, A);
        if (co_ >= 16){
            gemm_kernel<<<(9000+63)/64, 256>>>(A,  kc[i], ocb, 9000, co_, 64*ci);
            gemm_kernel<<<(9000+63)/64, 256>>>(hb, wd[i], odb, 9000, co_, ci);
        } else {
            dotn_kernel<<<(9000+7)/8, 256, (size_t)64*ci*co_*4>>>(A,  kc[i], ocb, 9000, co_, 64*ci);
            dotn_kernel<<<(9000+7)/8, 256, (size_t)ci*co_*4>>>(hb, wd[i], odb, 9000, co_, ci);
        }
        const float* prev = (i==1 || i==2) ? cur : nullptr;
        combine_kernel<<<(9000*co_+255)/256, 256>>>(ocb, odb, bcp[i], bdp[i], prev, nxt, co_);
        float* t = cur; cur = nxt; nxt = t;
    }
    final_kernel<<<(NF*3+255)/256, 256>>>(cur, p1, p0, dout);
}

// round 6
// speedup vs baseline: 1.4576x; 1.4576x over previous
#include <cuda_runtime.h>
#include <math.h>
#include <stdint.h>

#define NF 3000
#define NB 1500
#define RAD2 9.0f
#define INV_R (1.0f/3.0f)
#define CAP 256
#define EPSF 1e-8f
#define FOUR_OVER_PI 1.2732395447351628f

// ---------------- static device scratch ----------------
__device__ float g_p1[NF*3];
__device__ float g_feat0[NF*9];
__device__ int   g_fcnt[NF];
__device__ int   g_fidx[NF*64];
__device__ int   g_fbase[NF*64];
__device__ float g_fw8[NF*512];
__device__ int   g_bcnt[NF];
__device__ int   g_bidx[NF*64];
__device__ int   g_bbase[NF*64];
__device__ float g_bw8[NF*512];
__device__ float g_A[(size_t)9000*6144];
__device__ float g_Abox[NF*64];
__device__ float g_cf[9000*32];
__device__ float g_co[NF*32];
__device__ float g_oc[2*9000*64];
__device__ float g_od[9000*64];
__device__ float g_out1[9000*96];
__device__ float g_out2[9000*96];

// ---------------- geometry ----------------
__device__ __forceinline__ float sgnf(float v){ return (v>0.f)?1.f:((v<0.f)?-1.f:0.f); }

__device__ __forceinline__ void ball_to_cube(float x,float y,float z,float&obx,float&oby,float&obz){
    float sq = x*x+y*y+z*z;
    float norm = sqrtf(fmaxf(sq,EPSF));
    float xy_sq = x*x+y*y;
    bool polar = (1.25f*z*z) > xy_sq;
    float s_p = sqrtf(3.0f*norm/(norm+fabsf(z)+EPSF));
    float s_e = norm / sqrtf(fmaxf(xy_sq,EPSF));
    float cx = polar ? x*s_p : x*s_e;
    float cy = polar ? y*s_p : y*s_e;
    float cz = polar ? sgnf(z)*norm : 1.5f*z;
    float nxy = sqrtf(fmaxf(cx*cx+cy*cy,EPSF));
    bool xdom = fabsf(cy) <= fabsf(cx);
    float sx = (fabsf(cx) > EPSF) ? cx : 1.0f;
    float sy = (fabsf(cy) > EPSF) ? cy : 1.0f;
    float bx1 = sgnf(cx)*nxy;
    float by1 = bx1*FOUR_OVER_PI*atanf(cy/sx);
    float by2 = sgnf(cy)*nxy;
    float bx2 = by2*FOUR_OVER_PI*atanf(cx/sy);
    float bx = xdom ? bx1 : bx2;
    float by = xdom ? by1 : by2;
    if (cx*cx+cy*cy < EPSF){ bx=0.f; by=0.f; }
    if (sq < EPSF){ bx=0.f; by=0.f; cz=0.f; }
    obx=bx; oby=by; obz=cz;
}

// ---------------- prep ----------------
__global__ void prep_kernel(const float* __restrict__ p0,const float* __restrict__ v0,
                            const float* __restrict__ a,const float* __restrict__ other,
                            const float* __restrict__ v0e,
                            float* __restrict__ p1,float* __restrict__ feat0,
                            float* __restrict__ outState){
    int i = blockIdx.x*blockDim.x + threadIdx.x;
    if (i >= NF) return;
#pragma unroll
    for (int d=0; d<3; d++){
        float vv0 = v0[i*3+d];
        float v1  = vv0 + 0.1f*a[i*3+d];
        float pp1 = p0[i*3+d] + 0.1f*(vv0+v1)*0.5f;
        p1[i*3+d]        = pp1;
        feat0[i*9+d]     = v1;
        feat0[i*9+3+d]   = other[i*3+d];
        feat0[i*9+6+d]   = v0e[i*3+d];
        outState[i*3+d]  = v0e[i*3+d];
    }
}

// ---------------- neighbor search: exact top-64 by (d2, idx), then sort by base cell ----------------
__global__ void neigh_kernel(const float* __restrict__ pin, int Mp,
                             const float* __restrict__ pout,
                             const float* __restrict__ mask, int selfEx,
                             int* __restrict__ cntO, int* __restrict__ idxO,
                             int* __restrict__ baseO, float* __restrict__ w8O){
    __shared__ float cd2[CAP];
    __shared__ int   cid[CAP];
    __shared__ unsigned long long keys[CAP];
    __shared__ int scnt;
    __shared__ int   sM[64];
    __shared__ int   sB[64];
    __shared__ float sW8[64*8];
    __shared__ unsigned skey[64];
    int n = blockIdx.x, tid = threadIdx.x;
    float qx = pout[n*3], qy = pout[n*3+1], qz = pout[n*3+2];
    if (tid==0) scnt = 0;
    __syncthreads();
    for (int m = tid; m < Mp; m += blockDim.x){
        if (selfEx && m==n) continue;
        if (mask && !(mask[m] > 0.f)) continue;
        float dx = pin[m*3]-qx, dy = pin[m*3+1]-qy, dz = pin[m*3+2]-qz;
        float d2 = dx*dx + dy*dy + dz*dz;
        if (d2 <= RAD2){
            int p = atomicAdd(&scnt, 1);
            if (p < CAP){ cd2[p]=d2; cid[p]=m; }
        }
    }
    __syncthreads();
    int cn = min(scnt, CAP);
    for (int t = tid; t < CAP; t += blockDim.x)
        keys[t] = (t < cn) ? ((((unsigned long long)__float_as_uint(cd2[t]))<<32) | (unsigned)cid[t])
                           : 0xFFFFFFFFFFFFFFFFull;
    __syncthreads();
    for (int k = 2; k <= CAP; k <<= 1){
        for (int j = k>>1; j > 0; j >>= 1){
            int i = ((tid & ~(j-1)) << 1) | (tid & (j-1));
            int ixj = i | j;
            bool asc = ((i & k) == 0);
            unsigned long long av = keys[i], bv = keys[ixj];
            if ((av > bv) == asc){ keys[i]=bv; keys[ixj]=av; }
            __syncthreads();
        }
    }
    int keep = min(cn, 64);
    if (tid==0) cntO[n] = keep;
    // stage kept neighbors: compute base + 8 weights
    for (int t = tid; t < keep; t += blockDim.x){
        unsigned long long key = keys[t];
        int m = (int)(key & 0xFFFFFFFFull);
        float dx = pin[m*3]-qx, dy = pin[m*3+1]-qy, dz = pin[m*3+2]-qz;
        float ux = dx*INV_R, uy = dy*INV_R, uz = dz*INV_R;
        float r2 = ux*ux + uy*uy + uz*uz;
        float t1 = 1.f - r2;
        float win = fminf(fmaxf(t1*t1*t1, 0.f), 1.f);
        float bx, by, bz;
        ball_to_cube(ux, uy, uz, bx, by, bz);
        float cxx = fminf(fmaxf((bx*0.5f+0.5f)*3.f, 0.f), 3.f);
        float cyy = fminf(fmaxf((by*0.5f+0.5f)*3.f, 0.f), 3.f);
        float czz = fminf(fmaxf((bz*0.5f+0.5f)*3.f, 0.f), 3.f);
        int c0x = min((int)floorf(cxx), 2);
        int c0y = min((int)floorf(cyy), 2);
        int c0z = min((int)floorf(czz), 2);
        float fx = cxx - (float)c0x, fy = cyy - (float)c0y, fz = czz - (float)c0z;
        sM[t] = m;
        sB[t] = (c0x*4 + c0y)*4 + c0z;
        float gx[2] = {1.f-fx, fx}, gy[2] = {1.f-fy, fy}, gz[2] = {1.f-fz, fz};
        int jj = 0;
        for (int i2=0;i2<2;i2++) for (int j2=0;j2<2;j2++) for (int l2=0;l2<2;l2++)
            sW8[t*8 + (jj++)] = gx[i2]*gy[j2]*gz[l2]*win;
    }
    for (int t = tid; t < 64; t += blockDim.x)
        skey[t] = (t < keep) ? (unsigned)((sB[t] << 6) | t) : 0xFFFFFFFFu;
    __syncthreads();
    // sort 64 keys by (base, rank)
    for (int k = 2; k <= 64; k <<= 1){
        for (int j = k>>1; j > 0; j >>= 1){
            if (tid < 32){
                int i = ((tid & ~(j-1)) << 1) | (tid & (j-1));
                int ixj = i | j;
                bool asc = ((i & k) == 0);
                unsigned av = skey[i], bv = skey[ixj];
                if ((av > bv) == asc){ skey[i]=bv; skey[ixj]=av; }
            }
            __syncthreads();
        }
    }
    for (int t = tid; t < keep; t += blockDim.x){
        int s = (int)(skey[t] & 63u);
        idxO[n*64+t]  = sM[s];
        baseO[n*64+t] = sB[s];
#pragma unroll
        for (int j=0;j<8;j++) w8O[n*512 + t*8 + j] = sW8[s*8 + j];
    }
}

// ---------------- scatter (big): float4, register run-accumulation ----------------
// blockDim >= F/4; thread f4 owns one float4 column and all 8 corners (race-free).
__global__ void scatter_big(const float* __restrict__ feats, int F, int C, int S,
                            const int* __restrict__ cnt, const int* __restrict__ nidx,
                            const int* __restrict__ nbase, const float* __restrict__ nw8,
                            float* __restrict__ A, int reluA){
    extern __shared__ float acc[];           // 64*F floats
    __shared__ int sIdx[64]; __shared__ int sBase[64]; __shared__ float sW[512];
    float4* acc4 = (float4*)acc;
    int n = blockIdx.x, tid = threadIdx.x, bd = blockDim.x;
    int F4 = F >> 2;
    int cn = cnt[n];
    for (int e = tid; e < 64*F4; e += bd) acc4[e] = make_float4(0.f,0.f,0.f,0.f);
    for (int e = tid; e < cn; e += bd){ sIdx[e] = nidx[n*64+e]; sBase[e] = nbase[n*64+e]; }
    for (int e = tid; e < cn*8; e += bd) sW[e] = nw8[n*512+e];
    __syncthreads();
    const int coff[8] = {0,1,4,5,16,17,20,21};
    int f4 = tid;
    if (f4 < F4){
        float4 r[8];
        int prevb = -1;
        for (int k = 0; k < cn; k++){
            int b = sBase[k];
            if (b != prevb){
                if (prevb >= 0){
#pragma unroll
                    for (int j=0;j<8;j++){
                        int ai = (prevb + coff[j])*F4 + f4;
                        float4 t = acc4[ai];
                        t.x += r[j].x; t.y += r[j].y; t.z += r[j].z; t.w += r[j].w;
                        acc4[ai] = t;
                    }
                }
                prevb = b;
#pragma unroll
                for (int j=0;j<8;j++) r[j] = make_float4(0.f,0.f,0.f,0.f);
            }
            float4 fv = ((const float4*)(feats + (size_t)sIdx[k]*F))[f4];
            if (reluA){
                fv.x = fmaxf(fv.x,0.f); fv.y = fmaxf(fv.y,0.f);
                fv.z = fmaxf(fv.z,0.f); fv.w = fmaxf(fv.w,0.f);
            }
#pragma unroll
            for (int j=0;j<8;j++){
                float w = sW[k*8+j];
                r[j].x += w*fv.x; r[j].y += w*fv.y; r[j].z += w*fv.z; r[j].w += w*fv.w;
            }
        }
        if (prevb >= 0){
#pragma unroll
            for (int j=0;j<8;j++){
                int ai = (prevb + coff[j])*F4 + f4;
                float4 t = acc4[ai];
                t.x += r[j].x; t.y += r[j].y; t.z += r[j].z; t.w += r[j].w;
                acc4[ai] = t;
            }
        }
    }
    __syncthreads();
    // A[(n*S+s)*64C + l*C + c] = acc[l*F + s*C + c]   (C%4==0 here)
    int KC = 64*C;
    float4* A4 = (float4*)A;
    for (int e4 = tid; e4 < 64*F4; e4 += bd){
        int l = e4 / F4, fl = e4 - l*F4;
        int f = fl*4;
        int s = f / C, c = f - s*C;
        A4[(((size_t)(n*S+s))*KC + l*C + c) >> 2] = acc4[e4];
    }
}

// ---------------- scatter (small F: 9 or 1) ----------------
__global__ void scatter_small(const float* __restrict__ feats, int F, int C, int S,
                              const int* __restrict__ cnt, const int* __restrict__ nidx,
                              const int* __restrict__ nbase, const float* __restrict__ nw8,
                              float* __restrict__ A){
    extern __shared__ float acc[];
    __shared__ int sIdx[64]; __shared__ int sBase[64]; __shared__ float sW[512];
    int n = blockIdx.x, tid = threadIdx.x;
    int cn = cnt[n];
    for (int e = tid; e < 64*F; e += blockDim.x) acc[e] = 0.f;
    if (tid < cn){ sIdx[tid] = nidx[n*64+tid]; sBase[tid] = nbase[n*64+tid]; }
    for (int e = tid; e < cn*8; e += blockDim.x) sW[e] = nw8[n*512+e];
    __syncthreads();
    const int coff[8] = {0,1,4,5,16,17,20,21};
    for (int k = 0; k < cn; k++){
        int ik = sIdx[k], b = sBase[k];
        for (int it = tid; it < 8*F; it += blockDim.x){
            int j = it / F, f = it - j*F;
            acc[(b+coff[j])*F+f] += sW[k*8+j] * feats[(size_t)ik*F+f];
        }
        __syncthreads();
    }
    int KC = 64*C;
    for (int e = tid; e < 64*F; e += blockDim.x){
        int l = e / F, f = e - l*F;
        int s = f / C, c = f - s*C;
        A[(size_t)(n*S+s)*KC + l*C + c] = acc[e];
    }
}

// ---------------- pipelined fp32 GEMM: C = A(MxK) @ B(Kx64), split-K via grid.y ----------------
__global__ __launch_bounds__(256) void gemm_pipe(const float* __restrict__ A,
                                                 const float* __restrict__ B,
                                                 float* __restrict__ Cc,
                                                 int M, int K, int reluA){
    __shared__ float As[2][16][64];
    __shared__ float Bs[2][16][64];
    int tid = threadIdx.x;
    int bm = blockIdx.x * 64;
    int kLen = K / gridDim.y;
    int kBeg = blockIdx.y * kLen;
    int T = kLen >> 4;
    float* Cout = Cc + (size_t)blockIdx.y * M * 64;

    int arl = tid >> 2;                  // 0..63 local row
    int arow = min(bm + arl, M-1);
    int aK  = (tid & 3) * 4;
    int brow = tid >> 4;                 // 0..15
    int bcol = (tid & 15) * 4;
    int tm = tid >> 4, tn = tid & 15;

    const float* Aptr = A + (size_t)arow*K + kBeg + aK;
    const float* Bptr = B + (size_t)(kBeg + brow)*64 + bcol;

    float4 a4, b4;
    // prologue
    a4 = *(const float4*)(Aptr);
    b4 = *(const float4*)(Bptr);
    if (reluA){
        a4.x=fmaxf(a4.x,0.f); a4.y=fmaxf(a4.y,0.f); a4.z=fmaxf(a4.z,0.f); a4.w=fmaxf(a4.w,0.f);
    }
    As[0][aK+0][arl]=a4.x; As[0][aK+1][arl]=a4.y; As[0][aK+2][arl]=a4.z; As[0][aK+3][arl]=a4.w;
    *(float4*)&Bs[0][brow][bcol] = b4;
    __syncthreads();

    float accv[4][4] = {};
    for (int t = 0; t < T; t++){
        int cb = t & 1;
        if (t+1 < T){
            a4 = *(const float4*)(Aptr + (t+1)*16);
            b4 = *(const float4*)(Bptr + (size_t)(t+1)*16*64);
            if (reluA){
                a4.x=fmaxf(a4.x,0.f); a4.y=fmaxf(a4.y,0.f); a4.z=fmaxf(a4.z,0.f); a4.w=fmaxf(a4.w,0.f);
            }
        }
#pragma unroll
        for (int kk = 0; kk < 16; kk++){
            float4 av = *(const float4*)&As[cb][kk][tm*4];
            float4 bv = *(const float4*)&Bs[cb][kk][tn*4];
            float ar[4] = {av.x, av.y, av.z, av.w};
            float br[4] = {bv.x, bv.y, bv.z, bv.w};
#pragma unroll
            for (int i=0;i<4;i++)
#pragma unroll
                for (int j=0;j<4;j++) accv[i][j] += ar[i]*br[j];
        }
        if (t+1 < T){
            int nb = cb ^ 1;
            As[nb][aK+0][arl]=a4.x; As[nb][aK+1][arl]=a4.y; As[nb][aK+2][arl]=a4.z; As[nb][aK+3][arl]=a4.w;
            *(float4*)&Bs[nb][brow][bcol] = b4;
            __syncthreads();
        }
    }
#pragma unroll
    for (int i=0;i<4;i++){
        int r = bm + tm*4 + i;
        if (r >= M) continue;
#pragma unroll
        for (int j=0;j<4;j++) Cout[(size_t)r*64 + tn*4 + j] = accv[i][j];
    }
}

// ---------------- simple GEMM for N=32 small cases ----------------
__global__ void gemm32(const float* __restrict__ A, const float* __restrict__ B,
                       float* __restrict__ Cc, int M, int N, int K){
    __shared__ float As[16][64];
    __shared__ float Bs[16][64];
    int tid = threadIdx.x;
    int bm = blockIdx.x * 64;
    int tm = tid >> 4, tn = tid & 15;
    float accv[4][4] = {};
    int arow = bm + (tid >> 2);
    int akq  = (tid & 3) * 4;
    int brow = tid >> 4;
    int bcol = (tid & 15) * 4;
    for (int k0 = 0; k0 < K; k0 += 16){
        float4 a4 = make_float4(0.f,0.f,0.f,0.f);
        if (arow < M) a4 = *(const float4*)(A + (size_t)arow*K + k0 + akq);
        float4 b4 = make_float4(0.f,0.f,0.f,0.f);
        if (bcol < N) b4 = *(const float4*)(B + (size_t)(k0+brow)*N + bcol);
        __syncthreads();
        int lr = tid >> 2;
        As[akq+0][lr] = a4.x; As[akq+1][lr] = a4.y; As[akq+2][lr] = a4.z; As[akq+3][lr] = a4.w;
        *(float4*)&Bs[brow][bcol] = b4;
        __syncthreads();
#pragma unroll
        for (int kk = 0; kk < 16; kk++){
            float4 av = *(const float4*)&As[kk][tm*4];
            float4 bv = *(const float4*)&Bs[kk][tn*4];
            float ar[4] = {av.x, av.y, av.z, av.w};
            float br[4] = {bv.x, bv.y, bv.z, bv.w};
#pragma unroll
            for (int i=0;i<4;i++)
#pragma unroll
                for (int j=0;j<4;j++) accv[i][j] += ar[i]*br[j];
        }
    }
#pragma unroll
    for (int i=0;i<4;i++){
        int r = bm + tm*4 + i;
        if (r >= M) continue;
#pragma unroll
        for (int j=0;j<4;j++){
            int c = tn*4 + j;
            if (c < N) Cc[(size_t)r*N + c] = accv[i][j];
        }
    }
}

// ---------------- dot kernel for N<=3 ----------------
__global__ void dotn_kernel(const float* __restrict__ A, const float* __restrict__ B,
                            float* __restrict__ Cc, int M, int N, int K, int reluA){
    extern __shared__ float sB[];
    int tid = threadIdx.x;
    for (int i = tid; i < K*N; i += blockDim.x) sB[i] = B[i];
    __syncthreads();
    int w = tid >> 5, lane = tid & 31;
    int r = blockIdx.x * 8 + w;
    if (r >= M) return;
    float a0=0.f, a1=0.f, a2=0.f;
    const float* ap = A + (size_t)r*K;
    for (int k = lane; k < K; k += 32){
        float av = ap[k];
        if (reluA) av = fmaxf(av, 0.f);
        a0 += av * sB[k*N+0];
        if (N > 1) a1 += av * sB[k*N+1];
        if (N > 2) a2 += av * sB[k*N+2];
    }
    for (int off=16; off; off>>=1){
        a0 += __shfl_down_sync(0xffffffffu, a0, off);
        a1 += __shfl_down_sync(0xffffffffu, a1, off);
        a2 += __shfl_down_sync(0xffffffffu, a2, off);
    }
    if (lane == 0){
        Cc[(size_t)r*N+0] = a0;
        if (N > 1) Cc[(size_t)r*N+1] = a1;
        if (N > 2) Cc[(size_t)r*N+2] = a2;
    }
}

// ---------------- elementwise ----------------
__global__ void combine0_kernel(const float* __restrict__ co, const float* __restrict__ cf,
                                const float* __restrict__ feat0,
                                const float* __restrict__ b0o, const float* __restrict__ b0f,
                                const float* __restrict__ wdf, const float* __restrict__ bdf,
                                float* __restrict__ out){
    int e = blockIdx.x*blockDim.x + threadIdx.x;
    if (e >= 9000*96) return;
    int row = e / 96, o = e - row*96;
    int n = row / 3;
    float v;
    if (o < 32) v = co[n*32+o] + b0o[o];
    else if (o < 64) v = cf[(size_t)row*32 + (o-32)] + b0f[o-32];
    else {
        int oo = o - 64;
        v = bdf[oo];
        for (int c=0;c<3;c++) v += feat0[row*3+c]*wdf[c*32+oo];
    }
    out[e] = v;
}

__global__ void combine_kernel(const float* __restrict__ oc, const float* __restrict__ oc2,
                               const float* __restrict__ od,
                               const float* __restrict__ bc, const float* __restrict__ bd,
                               const float* __restrict__ prev, float* __restrict__ out, int C){
    int e = blockIdx.x*blockDim.x + threadIdx.x;
    if (e >= 9000*C) return;
    int o = e % C;
    float v = oc[e] + bc[o] + od[e] + bd[o];
    if (oc2)  v += oc2[e];
    if (prev) v += prev[e];
    out[e] = v;
}

__global__ void final_kernel(const float* __restrict__ out4, const float* __restrict__ p1,
                             const float* __restrict__ p0, float* __restrict__ dout){
    int e = blockIdx.x*blockDim.x + threadIdx.x;
    if (e >= NF*3) return;
    int n = e/3, d = e - n*3;
    float pc0 = out4[(n*3+0)*3+d] * 0.25f * (1.0f/16.0f);
    float pc1 = out4[(n*3+1)*3+d] * 0.25f;
    float pc2 = out4[(n*3+2)*3+d] * 0.25f;
    float p_c = p1[e] + pc0;
    dout[e] = p_c;
    dout[9000 + e] = (p_c - p0[e]) / 0.1f;
    dout[18000 + n*6 + d]     = pc1;
    dout[18000 + n*6 + 3 + d] = pc2;
}

// ---------------- launch ----------------
extern "C" void kernel_launch(void* const* d_in, const int* in_sizes, int n_in,
                              void* d_out, int out_size){
    const float* v0e  = (const float*)d_in[1];
    const float* p0   = (const float*)d_in[2];
    const float* v0   = (const float*)d_in[3];
    const float* a    = (const float*)d_in[4];
    const float* other= (const float*)d_in[5];
    const float* box  = (const float*)d_in[6];
    const float* boxf = (const float*)d_in[7];
    const float* bmask= (const float*)d_in[9];
    const float* k0f  = (const float*)d_in[10];
    const float* b0f  = (const float*)d_in[11];
    const float* k0o  = (const float*)d_in[12];
    const float* b0o  = (const float*)d_in[13];
    const float* wdf  = (const float*)d_in[14];
    const float* bdf  = (const float*)d_in[15];
    const float *kc[4], *bcp[4], *wd[4], *bdp[4];
    if (in_sizes[18] == 262144){
        for (int i=0;i<4;i++){
            kc[i]=(const float*)d_in[16+2*i]; bcp[i]=(const float*)d_in[17+2*i];
            wd[i]=(const float*)d_in[24+2*i]; bdp[i]=(const float*)d_in[25+2*i];
        }
    } else {
        for (int i=0;i<4;i++){
            kc[i]=(const float*)d_in[16+4*i]; bcp[i]=(const float*)d_in[17+4*i];
            wd[i]=(const float*)d_in[18+4*i]; bdp[i]=(const float*)d_in[19+4*i];
        }
    }
    float* dout = (float*)d_out;

    float *p1, *feat0, *A, *Abox, *cfb, *cob, *ocb, *odb, *o1, *o2, *fw8, *bw8;
    int *fcnt, *fidx, *fbase, *bcnt, *bidx, *bbase;
    cudaGetSymbolAddress((void**)&p1, g_p1);
    cudaGetSymbolAddress((void**)&feat0, g_feat0);
    cudaGetSymbolAddress((void**)&A, g_A);
    cudaGetSymbolAddress((void**)&Abox, g_Abox);
    cudaGetSymbolAddress((void**)&cfb, g_cf);
    cudaGetSymbolAddress((void**)&cob, g_co);
    cudaGetSymbolAddress((void**)&ocb, g_oc);
    cudaGetSymbolAddress((void**)&odb, g_od);
    cudaGetSymbolAddress((void**)&o1, g_out1);
    cudaGetSymbolAddress((void**)&o2, g_out2);
    cudaGetSymbolAddress((void**)&fw8, g_fw8);
    cudaGetSymbolAddress((void**)&bw8, g_bw8);
    cudaGetSymbolAddress((void**)&fcnt, g_fcnt);
    cudaGetSymbolAddress((void**)&fidx, g_fidx);
    cudaGetSymbolAddress((void**)&fbase, g_fbase);
    cudaGetSymbolAddress((void**)&bcnt, g_bcnt);
    cudaGetSymbolAddress((void**)&bidx, g_bidx);
    cudaGetSymbolAddress((void**)&bbase, g_bbase);

    cudaFuncSetAttribute(scatter_big,  cudaFuncAttributeMaxDynamicSharedMemorySize, 80000);
    cudaFuncSetAttribute(dotn_kernel,  cudaFuncAttributeMaxDynamicSharedMemorySize, 50000);

    prep_kernel<<<(NF+127)/128, 128>>>(p0, v0, a, other, v0e, p1, feat0, dout + 36000);
    neigh_kernel<<<NF, 128>>>(p1, NF, p1, nullptr, 1, fcnt, fidx, fbase, fw8);
    neigh_kernel<<<NF, 128>>>(box, NB, p1, bmask, 0, bcnt, bidx, bbase, bw8);

    // layer 0
    scatter_small<<<NF, 256, 64*9*4>>>(feat0, 9, 3, 3, fcnt, fidx, fbase, fw8, A);
    gemm32<<<(9000+63)/64, 256>>>(A, k0f, cfb, 9000, 32, 192);
    scatter_small<<<NF, 256, 64*1*4>>>(boxf, 1, 1, 1, bcnt, bidx, bbase, bw8, Abox);
    gemm32<<<(3000+63)/64, 256>>>(Abox, k0o, cob, 3000, 32, 64);
    combine0_kernel<<<(9000*96+255)/256, 256>>>(cob, cfb, feat0, b0o, b0f, wdf, bdf, o1);

    int Cin[4]  = {96, 64, 64, 64};
    int Cout[4] = {64, 64, 64, 3};
    float* cur = o1; float* nxt = o2;
    for (int i=0;i<4;i++){
        int ci = Cin[i], co_ = Cout[i];
        int F = 3*ci, F4 = F/4;
        int bD = ((F4 + 31)/32)*32;
        scatter_big<<<NF, bD, (size_t)64*F*4>>>(cur, F, ci, 3, fcnt, fidx, fbase, fw8, A, 1);
        if (co_ == 64){
            gemm_pipe<<<dim3(141,2), 256>>>(A,  kc[i], ocb, 9000, 64*ci, 0);
            gemm_pipe<<<dim3(141,1), 256>>>(cur, wd[i], odb, 9000, ci, 1);
            combine_kernel<<<(9000*64+255)/256, 256>>>(ocb, ocb + (size_t)9000*64, odb,
                bcp[i], bdp[i], (i==1||i==2) ? cur : nullptr, nxt, 64);
        } else {
            dotn_kernel<<<(9000+7)/8, 256, (size_t)64*ci*co_*4>>>(A,  kc[i], ocb, 9000, co_, 64*ci, 0);
            dotn_kernel<<<(9000+7)/8, 256, (size_t)ci*co_*4>>>(cur, wd[i], odb, 9000, co_, ci, 1);
            combine_kernel<<<(9000*co_+255)/256, 256>>>(ocb, nullptr, odb,
                bcp[i], bdp[i], nullptr, nxt, co_);
        }
        float* t = cur; cur = nxt; nxt = t;
    }
    final_kernel<<<(NF*3+255)/256, 256>>>(cur, p1, p0, dout);
}